// round 1
// baseline (speedup 1.0000x reference)
#include <cuda_runtime.h>
#include <math.h>

#define N_A 50000
#define N_P 100000
#define HID 64
#define OUT_DIM 16
#define NE 2000000
#define HOP 3

// ---------------- scratch (device globals; no allocation allowed) ----------------
__device__ float g_xa[(size_t)N_A * HID];
__device__ float g_xp[(size_t)N_P * HID];
__device__ float g_ha[(size_t)N_A * HID];
__device__ float g_hp[(size_t)N_P * HID];
__device__ float g_agga[(size_t)N_A * HID];
__device__ float g_aggp1[(size_t)N_P * HID];
__device__ float g_aggp2[(size_t)N_P * HID];

__device__ int g_rp_ap[N_A + 1];
__device__ int g_rp_pa[N_P + 1];
__device__ int g_rp_pp[N_P + 1];
__device__ int g_col_ap[NE];
__device__ int g_col_pa[NE];
__device__ int g_col_pp[NE];
__device__ int g_cnt[N_P];
__device__ int g_cursor[N_P];

__device__ float g_x1a[N_A],  g_w2a[N_A],  g_h1p_ap[N_P];
__device__ float g_x1pa[N_P], g_w2pa[N_P], g_h1a[N_A];
__device__ float g_x1pp[N_P], g_w2pp[N_P], g_h1p_pp[N_P];

// ---------------- CSR build ----------------
__global__ void hist_k(const int* __restrict__ s, int* cnt, int e) {
    int i = blockIdx.x * blockDim.x + threadIdx.x;
    if (i < e) atomicAdd(&cnt[s[i]], 1);
}

// single-block exclusive scan (n <= 100000); rowptr[n] = total
__global__ void scan_k(const int* __restrict__ cnt, int* __restrict__ rowptr, int n) {
    __shared__ int sd[1024];
    int tid = threadIdx.x;
    int carry = 0;
    for (int base = 0; base < n; base += 1024) {
        int i = base + tid;
        int v = (i < n) ? cnt[i] : 0;
        sd[tid] = v;
        __syncthreads();
        for (int off = 1; off < 1024; off <<= 1) {
            int t = (tid >= off) ? sd[tid - off] : 0;
            __syncthreads();
            sd[tid] += t;
            __syncthreads();
        }
        int incl = sd[tid];
        int total = sd[1023];
        if (i < n) rowptr[i] = carry + incl - v;
        carry += total;
        __syncthreads();
    }
    if (tid == 0) rowptr[n] = carry;
}

__global__ void scatter_k(const int* __restrict__ s, const int* __restrict__ t,
                          int* cursor, int* __restrict__ col, int e) {
    int i = blockIdx.x * blockDim.x + threadIdx.x;
    if (i < e) {
        int p = atomicAdd(&cursor[s[i]], 1);
        col[p] = t[i];
    }
}

// ---------------- fc1: out = relu(x @ W + b), W is [D,64] ----------------
// 16 threads per node, 4 output cols each (float4 on W rows).
__global__ void fc1_k(const float* __restrict__ x, const float* __restrict__ W,
                      const float* __restrict__ b, float* __restrict__ out,
                      int n, int D) {
    int node = blockIdx.x * 16 + (threadIdx.x >> 4);
    int c4 = (threadIdx.x & 15) * 4;
    if (node >= n) return;
    const float* xr = x + (size_t)node * D;
    float4 acc = *(const float4*)(b + c4);
#pragma unroll 8
    for (int k = 0; k < D; k++) {
        float xv = __ldg(xr + k);
        float4 w4 = *(const float4*)(W + (size_t)k * HID + c4);
        acc.x = fmaf(xv, w4.x, acc.x);
        acc.y = fmaf(xv, w4.y, acc.y);
        acc.z = fmaf(xv, w4.z, acc.z);
        acc.w = fmaf(xv, w4.w, acc.w);
    }
    acc.x = fmaxf(acc.x, 0.f);
    acc.y = fmaxf(acc.y, 0.f);
    acc.z = fmaxf(acc.z, 0.f);
    acc.w = fmaxf(acc.w, 0.f);
    *(float4*)(out + (size_t)node * HID + c4) = acc;
}

// ---------------- per-node scalars ----------------
// x1 = x @ a1 ; w2 = exp(lrelu(x1 + x @ a2))   (warp per node)
__global__ void src_scalar_k(const float* __restrict__ x, const float* __restrict__ a1,
                             const float* __restrict__ a2, float* __restrict__ x1,
                             float* __restrict__ w2, int n) {
    int w = (blockIdx.x * blockDim.x + threadIdx.x) >> 5;
    int lane = threadIdx.x & 31;
    if (w >= n) return;
    float v0 = x[(size_t)w * HID + lane];
    float v1 = x[(size_t)w * HID + 32 + lane];
    float p1 = v0 * a1[lane] + v1 * a1[32 + lane];
    float p2 = v0 * a2[lane] + v1 * a2[32 + lane];
#pragma unroll
    for (int off = 16; off; off >>= 1) {
        p1 += __shfl_xor_sync(0xffffffffu, p1, off);
        p2 += __shfl_xor_sync(0xffffffffu, p2, off);
    }
    if (lane == 0) {
        x1[w] = p1;
        float sc = p1 + p2;
        sc = sc >= 0.f ? sc : 0.2f * sc;
        w2[w] = __expf(sc);
    }
}

// h1 = h @ a2   (warp per node)
__global__ void tgt_scalar_k(const float* __restrict__ h, const float* __restrict__ a2,
                             float* __restrict__ h1, int n) {
    int w = (blockIdx.x * blockDim.x + threadIdx.x) >> 5;
    int lane = threadIdx.x & 31;
    if (w >= n) return;
    float v0 = h[(size_t)w * HID + lane];
    float v1 = h[(size_t)w * HID + 32 + lane];
    float p = v0 * a2[lane] + v1 * a2[32 + lane];
#pragma unroll
    for (int off = 16; off; off >>= 1) p += __shfl_xor_sync(0xffffffffu, p, off);
    if (lane == 0) h1[w] = p;
}

// ---------------- edge aggregation: warp per source node, CSR gather ----------------
// agg[n] = (sum_e w1_e * h[t_e] + w2[n]*x[n]) / (sum_e w1_e + w2[n])
__global__ void agg_k(const int* __restrict__ rowptr, const int* __restrict__ col,
                      const float* __restrict__ x1, const float* __restrict__ w2,
                      const float* __restrict__ h1, const float* __restrict__ h,
                      const float* __restrict__ x, float* __restrict__ agg, int ns) {
    int n = (blockIdx.x * blockDim.x + threadIdx.x) >> 5;
    int lane = threadIdx.x & 31;
    if (n >= ns) return;
    int beg = rowptr[n], end = rowptr[n + 1];
    float w2n = w2[n];
    float x1n = x1[n];
    float2 xv = ((const float2*)x)[(size_t)n * 32 + lane];
    float ax = w2n * xv.x;
    float ay = w2n * xv.y;
    float sumw = w2n;
    const float2* h2 = (const float2*)h;

    int j = beg;
    for (; j + 32 <= end; j += 32) {
        int tl = col[j + lane];
        float sc = x1n + __ldg(h1 + tl);
        sc = sc >= 0.f ? sc : 0.2f * sc;
        float wl = __expf(sc);
#pragma unroll
        for (int k = 0; k < 32; k++) {
            float w = __shfl_sync(0xffffffffu, wl, k);
            int t = __shfl_sync(0xffffffffu, tl, k);
            float2 hv = __ldg(&h2[(size_t)t * 32 + lane]);
            ax = fmaf(w, hv.x, ax);
            ay = fmaf(w, hv.y, ay);
            sumw += w;
        }
    }
    int rem = end - j;
    if (rem > 0) {
        int tl = 0;
        float wl = 0.f;
        if (lane < rem) {
            tl = col[j + lane];
            float sc = x1n + __ldg(h1 + tl);
            sc = sc >= 0.f ? sc : 0.2f * sc;
            wl = __expf(sc);
        }
        for (int k = 0; k < rem; k++) {
            float w = __shfl_sync(0xffffffffu, wl, k);
            int t = __shfl_sync(0xffffffffu, tl, k);
            float2 hv = __ldg(&h2[(size_t)t * 32 + lane]);
            ax = fmaf(w, hv.x, ax);
            ay = fmaf(w, hv.y, ay);
            sumw += w;
        }
    }
    float inv = 1.f / sumw;
    ((float2*)agg)[(size_t)n * 32 + lane] = make_float2(ax * inv, ay * inv);
}

// ---------------- combine ----------------
__global__ void elu_k(const float* __restrict__ a, float* __restrict__ h, int n) {
    int i = blockIdx.x * blockDim.x + threadIdx.x;
    if (i < n) {
        float v = a[i];
        h[i] = v > 0.f ? v : expm1f(v);
    }
}
__global__ void elu2_k(const float* __restrict__ a, const float* __restrict__ b,
                       float* __restrict__ h, int n) {
    int i = blockIdx.x * blockDim.x + threadIdx.x;
    if (i < n) {
        float v = 0.5f * (a[i] + b[i]);
        h[i] = v > 0.f ? v : expm1f(v);
    }
}

// ---------------- fc2: out = h @ W[64,16] + b ----------------
__global__ void fc2_k(const float* __restrict__ h, const float* __restrict__ W,
                      const float* __restrict__ b, float* __restrict__ out, int n) {
    int node = blockIdx.x * 16 + (threadIdx.x >> 4);
    int c = threadIdx.x & 15;
    if (node >= n) return;
    float acc = b[c];
    const float* hr = h + (size_t)node * HID;
#pragma unroll
    for (int k = 0; k < HID; k++)
        acc = fmaf(__ldg(hr + k), __ldg(W + k * OUT_DIM + c), acc);
    out[(size_t)node * OUT_DIM + c] = acc;
}

// ---------------- host ----------------
static inline int cdiv(int a, int b) { return (a + b - 1) / b; }

extern "C" void kernel_launch(void* const* d_in, const int* in_sizes, int n_in,
                              void* d_out, int out_size) {
    const float* x_a  = (const float*)d_in[0];
    const float* x_p  = (const float*)d_in[1];
    const int*   ap_s = (const int*)d_in[2];
    const int*   ap_t = (const int*)d_in[3];
    const int*   pa_s = (const int*)d_in[4];
    const int*   pa_t = (const int*)d_in[5];
    const int*   pp_s = (const int*)d_in[6];
    const int*   pp_t = (const int*)d_in[7];
    const float* f1aw = (const float*)d_in[8];
    const float* f1ab = (const float*)d_in[9];
    const float* f1pw = (const float*)d_in[10];
    const float* f1pb = (const float*)d_in[11];
    const float* f2w  = (const float*)d_in[12];
    const float* f2b  = (const float*)d_in[13];
    const float* a1ap = (const float*)d_in[14];
    const float* a2ap = (const float*)d_in[15];
    const float* a1pa = (const float*)d_in[16];
    const float* a2pa = (const float*)d_in[17];
    const float* a1pp = (const float*)d_in[18];
    const float* a2pp = (const float*)d_in[19];
    float* out = (float*)d_out;

    float *xa, *xp, *ha, *hp, *agga, *aggp1, *aggp2;
    int *rp_ap, *rp_pa, *rp_pp, *col_ap, *col_pa, *col_pp, *cnt, *cursor;
    float *x1a, *w2a, *h1p_ap, *x1pa, *w2pa, *h1a, *x1pp, *w2pp, *h1p_pp;
    cudaGetSymbolAddress((void**)&xa, g_xa);
    cudaGetSymbolAddress((void**)&xp, g_xp);
    cudaGetSymbolAddress((void**)&ha, g_ha);
    cudaGetSymbolAddress((void**)&hp, g_hp);
    cudaGetSymbolAddress((void**)&agga, g_agga);
    cudaGetSymbolAddress((void**)&aggp1, g_aggp1);
    cudaGetSymbolAddress((void**)&aggp2, g_aggp2);
    cudaGetSymbolAddress((void**)&rp_ap, g_rp_ap);
    cudaGetSymbolAddress((void**)&rp_pa, g_rp_pa);
    cudaGetSymbolAddress((void**)&rp_pp, g_rp_pp);
    cudaGetSymbolAddress((void**)&col_ap, g_col_ap);
    cudaGetSymbolAddress((void**)&col_pa, g_col_pa);
    cudaGetSymbolAddress((void**)&col_pp, g_col_pp);
    cudaGetSymbolAddress((void**)&cnt, g_cnt);
    cudaGetSymbolAddress((void**)&cursor, g_cursor);
    cudaGetSymbolAddress((void**)&x1a, g_x1a);
    cudaGetSymbolAddress((void**)&w2a, g_w2a);
    cudaGetSymbolAddress((void**)&h1p_ap, g_h1p_ap);
    cudaGetSymbolAddress((void**)&x1pa, g_x1pa);
    cudaGetSymbolAddress((void**)&w2pa, g_w2pa);
    cudaGetSymbolAddress((void**)&h1a, g_h1a);
    cudaGetSymbolAddress((void**)&x1pp, g_x1pp);
    cudaGetSymbolAddress((void**)&w2pp, g_w2pp);
    cudaGetSymbolAddress((void**)&h1p_pp, g_h1p_pp);

    cudaStream_t st = 0;
    const int TB = 256;
    const int EB = cdiv(NE, TB);

    // --- CSR build (once per launch; reused across hops) ---
    cudaMemsetAsync(cnt, 0, N_A * sizeof(int), st);
    hist_k<<<EB, TB, 0, st>>>(ap_s, cnt, NE);
    scan_k<<<1, 1024, 0, st>>>(cnt, rp_ap, N_A);
    cudaMemcpyAsync(cursor, rp_ap, N_A * sizeof(int), cudaMemcpyDeviceToDevice, st);
    scatter_k<<<EB, TB, 0, st>>>(ap_s, ap_t, cursor, col_ap, NE);

    cudaMemsetAsync(cnt, 0, N_P * sizeof(int), st);
    hist_k<<<EB, TB, 0, st>>>(pa_s, cnt, NE);
    scan_k<<<1, 1024, 0, st>>>(cnt, rp_pa, N_P);
    cudaMemcpyAsync(cursor, rp_pa, N_P * sizeof(int), cudaMemcpyDeviceToDevice, st);
    scatter_k<<<EB, TB, 0, st>>>(pa_s, pa_t, cursor, col_pa, NE);

    cudaMemsetAsync(cnt, 0, N_P * sizeof(int), st);
    hist_k<<<EB, TB, 0, st>>>(pp_s, cnt, NE);
    scan_k<<<1, 1024, 0, st>>>(cnt, rp_pp, N_P);
    cudaMemcpyAsync(cursor, rp_pp, N_P * sizeof(int), cudaMemcpyDeviceToDevice, st);
    scatter_k<<<EB, TB, 0, st>>>(pp_s, pp_t, cursor, col_pp, NE);

    // --- input projections ---
    fc1_k<<<cdiv(N_A, 16), TB, 0, st>>>(x_a, f1aw, f1ab, xa, N_A, 512);
    fc1_k<<<cdiv(N_P, 16), TB, 0, st>>>(x_p, f1pw, f1pb, xp, N_P, 256);
    cudaMemcpyAsync(ha, xa, (size_t)N_A * HID * sizeof(float), cudaMemcpyDeviceToDevice, st);
    cudaMemcpyAsync(hp, xp, (size_t)N_P * HID * sizeof(float), cudaMemcpyDeviceToDevice, st);

    const int WA = cdiv(N_A * 32, TB);   // warp-per-node grids
    const int WP = cdiv(N_P * 32, TB);

    for (int i = 0; i < HOP; i++) {
        const float* A1ap = a1ap + i * HID;
        const float* A2ap = a2ap + i * HID;
        const float* A1pa = a1pa + i * HID;
        const float* A2pa = a2pa + i * HID;
        const float* A1pp = a1pp + i * HID;
        const float* A2pp = a2pp + i * HID;

        src_scalar_k<<<WA, TB, 0, st>>>(xa, A1ap, A2ap, x1a, w2a, N_A);
        tgt_scalar_k<<<WP, TB, 0, st>>>(hp, A2ap, h1p_ap, N_P);
        src_scalar_k<<<WP, TB, 0, st>>>(xp, A1pa, A2pa, x1pa, w2pa, N_P);
        tgt_scalar_k<<<WA, TB, 0, st>>>(ha, A2pa, h1a, N_A);
        src_scalar_k<<<WP, TB, 0, st>>>(xp, A1pp, A2pp, x1pp, w2pp, N_P);
        tgt_scalar_k<<<WP, TB, 0, st>>>(hp, A2pp, h1p_pp, N_P);

        agg_k<<<WA, TB, 0, st>>>(rp_ap, col_ap, x1a, w2a, h1p_ap, hp, xa, agga, N_A);
        agg_k<<<WP, TB, 0, st>>>(rp_pa, col_pa, x1pa, w2pa, h1a, ha, xp, aggp1, N_P);
        agg_k<<<WP, TB, 0, st>>>(rp_pp, col_pp, x1pp, w2pp, h1p_pp, hp, xp, aggp2, N_P);

        elu_k<<<cdiv(N_A * HID, TB), TB, 0, st>>>(agga, ha, N_A * HID);
        elu2_k<<<cdiv(N_P * HID, TB), TB, 0, st>>>(aggp1, aggp2, hp, N_P * HID);
    }

    fc2_k<<<cdiv(N_A, 16), TB, 0, st>>>(ha, f2w, f2b, out, N_A);
}

// round 2
// speedup vs baseline: 1.3895x; 1.3895x over previous
#include <cuda_runtime.h>
#include <math.h>

#define N_A 50000
#define N_P 100000
#define HID 64
#define OUT_DIM 16
#define NE 2000000
#define HOP 3
#define SCAN_B 1024
#define MAXBLK 128

// ---------------- scratch (device globals) ----------------
__device__ float g_xa[(size_t)N_A * HID];    // projected A features (fixed per layer)
__device__ float g_xp[(size_t)N_P * HID];    // projected P features
__device__ float g_ha[(size_t)N_A * HID];    // hidden A
__device__ float g_hp0[(size_t)N_P * HID];   // hidden P double buffer
__device__ float g_hp1[(size_t)N_P * HID];
__device__ float g_aggp1[(size_t)N_P * HID]; // raw p<-a aggregation

__device__ int g_rp_ap[N_A + 1];
__device__ int g_rp_pa[N_P + 1];
__device__ int g_rp_pp[N_P + 1];
__device__ int g_col_ap[NE];
__device__ int g_col_pa[NE];
__device__ int g_col_pp[NE];
__device__ int g_cnt[N_A + 2 * N_P];
__device__ int g_cur_ap[N_A];
__device__ int g_cur_pa[N_P];
__device__ int g_cur_pp[N_P];
__device__ int g_bsum[3 * MAXBLK];

__device__ float g_h1a[N_A];     // h_a @ a2_pa  (current hop)
__device__ float g_h1ap[N_P];    // h_p @ a2_ap
__device__ float g_h1pp0[N_P];   // h_p @ a2_pp  (double buffered)
__device__ float g_h1pp1[N_P];

// ---------------- CSR build ----------------
__global__ void hist_k(const int* __restrict__ s, int* cnt, int e) {
    int i = blockIdx.x * blockDim.x + threadIdx.x;
    if (i < e) atomicAdd(&cnt[s[i]], 1);
}

__global__ void scan1_k(const int* __restrict__ cnt, int* __restrict__ rp,
                        int* __restrict__ bsum, int n) {
    __shared__ int sd[SCAN_B];
    int tid = threadIdx.x;
    int i = blockIdx.x * SCAN_B + tid;
    int v = (i < n) ? cnt[i] : 0;
    sd[tid] = v;
    __syncthreads();
#pragma unroll
    for (int o = 1; o < SCAN_B; o <<= 1) {
        int t = (tid >= o) ? sd[tid - o] : 0;
        __syncthreads();
        sd[tid] += t;
        __syncthreads();
    }
    if (i < n) rp[i] = sd[tid] - v;
    if (tid == SCAN_B - 1) bsum[blockIdx.x] = sd[tid];
}

__global__ void scan2_k(int* bsum, int nb, int* rp_last) {
    __shared__ int sd[128];
    int tid = threadIdx.x;
    int v = (tid < nb) ? bsum[tid] : 0;
    sd[tid] = v;
    __syncthreads();
#pragma unroll
    for (int o = 1; o < 128; o <<= 1) {
        int t = (tid >= o) ? sd[tid - o] : 0;
        __syncthreads();
        sd[tid] += t;
        __syncthreads();
    }
    if (tid < nb) bsum[tid] = sd[tid] - v;
    if (tid == 127) *rp_last = sd[127];
}

__global__ void scan3_k(int* __restrict__ rp, const int* __restrict__ bsum,
                        int* __restrict__ cur, int n) {
    int i = blockIdx.x * blockDim.x + threadIdx.x;
    if (i < n) {
        int r = rp[i] + bsum[i >> 10];
        rp[i] = r;
        cur[i] = r;
    }
}

__global__ void scatter_k(const int* __restrict__ s, const int* __restrict__ t,
                          int* cursor, int* __restrict__ col, int e) {
    int i = blockIdx.x * blockDim.x + threadIdx.x;
    if (i < e) {
        int p = atomicAdd(&cursor[s[i]], 1);
        col[p] = t[i];
    }
}

// ---------------- fc1: out = relu(x @ W + b), fused initial h1 dots ----------------
// 16 threads per node, 4 output cols each; k unrolled x4 with float4 loads.
template <int NDOT>
__global__ void fc1_k(const float* __restrict__ x, const float* __restrict__ W,
                      const float* __restrict__ b, float* __restrict__ out,
                      int n, int D,
                      const float* __restrict__ av1, const float* __restrict__ av2,
                      float* __restrict__ h1o1, float* __restrict__ h1o2) {
    int node = blockIdx.x * 16 + (threadIdx.x >> 4);
    int g = threadIdx.x & 15;
    if (node >= n) return;
    int c4 = g * 4;
    const float* xr = x + (size_t)node * D;
    float4 acc = *(const float4*)(b + c4);
#pragma unroll 2
    for (int k = 0; k < D; k += 4) {
        float4 xv = __ldg((const float4*)(xr + k));
        float4 w0 = __ldg((const float4*)(W + (size_t)k * HID + c4));
        float4 w1 = __ldg((const float4*)(W + (size_t)(k + 1) * HID + c4));
        float4 w2 = __ldg((const float4*)(W + (size_t)(k + 2) * HID + c4));
        float4 w3 = __ldg((const float4*)(W + (size_t)(k + 3) * HID + c4));
        acc.x = fmaf(xv.x, w0.x, fmaf(xv.y, w1.x, fmaf(xv.z, w2.x, fmaf(xv.w, w3.x, acc.x))));
        acc.y = fmaf(xv.x, w0.y, fmaf(xv.y, w1.y, fmaf(xv.z, w2.y, fmaf(xv.w, w3.y, acc.y))));
        acc.z = fmaf(xv.x, w0.z, fmaf(xv.y, w1.z, fmaf(xv.z, w2.z, fmaf(xv.w, w3.z, acc.z))));
        acc.w = fmaf(xv.x, w0.w, fmaf(xv.y, w1.w, fmaf(xv.z, w2.w, fmaf(xv.w, w3.w, acc.w))));
    }
    acc.x = fmaxf(acc.x, 0.f);
    acc.y = fmaxf(acc.y, 0.f);
    acc.z = fmaxf(acc.z, 0.f);
    acc.w = fmaxf(acc.w, 0.f);
    *(float4*)(out + (size_t)node * HID + c4) = acc;

    // initial h1 = h @ a2 (h == relu output here)
    float4 a = __ldg((const float4*)av1 + g);
    float d1 = acc.x * a.x + acc.y * a.y + acc.z * a.z + acc.w * a.w;
    float d2 = 0.f;
    if (NDOT == 2) {
        float4 a2 = __ldg((const float4*)av2 + g);
        d2 = acc.x * a2.x + acc.y * a2.y + acc.z * a2.z + acc.w * a2.w;
    }
#pragma unroll
    for (int o = 8; o; o >>= 1) {
        d1 += __shfl_xor_sync(0xffffffffu, d1, o);
        if (NDOT == 2) d2 += __shfl_xor_sync(0xffffffffu, d2, o);
    }
    if (g == 0) {
        h1o1[node] = d1;
        if (NDOT == 2) h1o2[node] = d2;
    }
}

// ---------------- fused edge aggregation ----------------
// warp per source node; half-warp per edge; float4 gathers.
// MODE 0: write raw agg (p<-a)
// MODE 1: write elu(agg) to ha, compute next-hop h1a dot
// MODE 2: write elu(0.5*(other+agg)) to hp_next, compute 2 next-hop dots
template <int MODE>
__global__ void __launch_bounds__(256)
agg_k(const int* __restrict__ rowptr, const int* __restrict__ col,
      const float* __restrict__ h1, const float4* __restrict__ h4,
      const float4* __restrict__ x4p,
      const float* __restrict__ a1, const float* __restrict__ a2,
      float4* __restrict__ out, const float4* __restrict__ other,
      const float* __restrict__ a2n1, const float* __restrict__ a2n2,
      float* __restrict__ h1n1, float* __restrict__ h1n2,
      int donext, int ns) {
    int n = (blockIdx.x * blockDim.x + threadIdx.x) >> 5;
    if (n >= ns) return;
    int lane = threadIdx.x & 31;
    int c = lane & 15;
    int hs = lane & 16;

    float4 xv = __ldg(x4p + (size_t)n * 16 + c);
    float4 a1v = __ldg((const float4*)a1 + c);
    float4 a2v = __ldg((const float4*)a2 + c);
    float p1 = xv.x * a1v.x + xv.y * a1v.y + xv.z * a1v.z + xv.w * a1v.w;
    float p2 = xv.x * a2v.x + xv.y * a2v.y + xv.z * a2v.z + xv.w * a2v.w;
#pragma unroll
    for (int o = 8; o; o >>= 1) {
        p1 += __shfl_xor_sync(0xffffffffu, p1, o);
        p2 += __shfl_xor_sync(0xffffffffu, p2, o);
    }
    float x1n = p1;
    float sc = p1 + p2;
    sc = sc >= 0.f ? sc : 0.2f * sc;
    float w2n = __expf(sc);

    int beg = __ldg(rowptr + n), end = __ldg(rowptr + n + 1);
    float4 acc = make_float4(0.f, 0.f, 0.f, 0.f);
    float sumw = 0.f;

    int j = beg;
    for (; j + 32 <= end; j += 32) {
        int tl = __ldg(col + j + lane);
        float s = x1n + __ldg(h1 + tl);
        s = s >= 0.f ? s : 0.2f * s;
        float wl = __expf(s);
#pragma unroll
        for (int k = 0; k < 16; k++) {
            float w = __shfl_sync(0xffffffffu, wl, hs + k);
            int t = __shfl_sync(0xffffffffu, tl, hs + k);
            float4 hv = __ldg(h4 + (size_t)t * 16 + c);
            acc.x = fmaf(w, hv.x, acc.x);
            acc.y = fmaf(w, hv.y, acc.y);
            acc.z = fmaf(w, hv.z, acc.z);
            acc.w = fmaf(w, hv.w, acc.w);
            sumw += w;
        }
    }
    if (j < end) {
        int idx = j + lane;
        int tl = 0;
        float wl = 0.f;
        if (idx < end) {
            tl = __ldg(col + idx);
            float s = x1n + __ldg(h1 + tl);
            s = s >= 0.f ? s : 0.2f * s;
            wl = __expf(s);
        }
#pragma unroll
        for (int k = 0; k < 16; k++) {
            float w = __shfl_sync(0xffffffffu, wl, hs + k);
            int t = __shfl_sync(0xffffffffu, tl, hs + k);
            if (j + hs + k < end) {
                float4 hv = __ldg(h4 + (size_t)t * 16 + c);
                acc.x = fmaf(w, hv.x, acc.x);
                acc.y = fmaf(w, hv.y, acc.y);
                acc.z = fmaf(w, hv.z, acc.z);
                acc.w = fmaf(w, hv.w, acc.w);
                sumw += w;
            }
        }
    }

    // combine halves
    acc.x += __shfl_xor_sync(0xffffffffu, acc.x, 16);
    acc.y += __shfl_xor_sync(0xffffffffu, acc.y, 16);
    acc.z += __shfl_xor_sync(0xffffffffu, acc.z, 16);
    acc.w += __shfl_xor_sync(0xffffffffu, acc.w, 16);
    sumw += __shfl_xor_sync(0xffffffffu, sumw, 16);

    // self term
    sumw += w2n;
    acc.x = fmaf(w2n, xv.x, acc.x);
    acc.y = fmaf(w2n, xv.y, acc.y);
    acc.z = fmaf(w2n, xv.z, acc.z);
    acc.w = fmaf(w2n, xv.w, acc.w);

    float inv = 1.f / sumw;
    float4 r = make_float4(acc.x * inv, acc.y * inv, acc.z * inv, acc.w * inv);

    if (MODE == 0) {
        if (!hs) out[(size_t)n * 16 + c] = r;
        return;
    }
    if (MODE == 2) {
        float4 o = __ldg(other + (size_t)n * 16 + c);
        r.x = 0.5f * (r.x + o.x);
        r.y = 0.5f * (r.y + o.y);
        r.z = 0.5f * (r.z + o.z);
        r.w = 0.5f * (r.w + o.w);
    }
    float4 v;
    v.x = r.x > 0.f ? r.x : expm1f(r.x);
    v.y = r.y > 0.f ? r.y : expm1f(r.y);
    v.z = r.z > 0.f ? r.z : expm1f(r.z);
    v.w = r.w > 0.f ? r.w : expm1f(r.w);
    if (!hs) out[(size_t)n * 16 + c] = v;

    if (donext) {
        float4 b1 = __ldg((const float4*)a2n1 + c);
        float d1 = v.x * b1.x + v.y * b1.y + v.z * b1.z + v.w * b1.w;
        float d2 = 0.f;
        if (MODE == 2) {
            float4 b2 = __ldg((const float4*)a2n2 + c);
            d2 = v.x * b2.x + v.y * b2.y + v.z * b2.z + v.w * b2.w;
        }
#pragma unroll
        for (int o = 8; o; o >>= 1) {
            d1 += __shfl_xor_sync(0xffffffffu, d1, o);
            if (MODE == 2) d2 += __shfl_xor_sync(0xffffffffu, d2, o);
        }
        if (lane == 0) {
            h1n1[n] = d1;
            if (MODE == 2) h1n2[n] = d2;
        }
    }
}

// ---------------- fc2: out = h @ W[64,16] + b ----------------
__global__ void fc2_k(const float* __restrict__ h, const float* __restrict__ W,
                      const float* __restrict__ b, float* __restrict__ out, int n) {
    int node = blockIdx.x * 16 + (threadIdx.x >> 4);
    int c = threadIdx.x & 15;
    if (node >= n) return;
    float acc = b[c];
    const float* hr = h + (size_t)node * HID;
#pragma unroll
    for (int k = 0; k < HID; k++)
        acc = fmaf(__ldg(hr + k), __ldg(W + k * OUT_DIM + c), acc);
    out[(size_t)node * OUT_DIM + c] = acc;
}

// ---------------- host ----------------
static inline int cdiv(int a, int b) { return (a + b - 1) / b; }

extern "C" void kernel_launch(void* const* d_in, const int* in_sizes, int n_in,
                              void* d_out, int out_size) {
    const float* x_a  = (const float*)d_in[0];
    const float* x_p  = (const float*)d_in[1];
    const int*   ap_s = (const int*)d_in[2];
    const int*   ap_t = (const int*)d_in[3];
    const int*   pa_s = (const int*)d_in[4];
    const int*   pa_t = (const int*)d_in[5];
    const int*   pp_s = (const int*)d_in[6];
    const int*   pp_t = (const int*)d_in[7];
    const float* f1aw = (const float*)d_in[8];
    const float* f1ab = (const float*)d_in[9];
    const float* f1pw = (const float*)d_in[10];
    const float* f1pb = (const float*)d_in[11];
    const float* f2w  = (const float*)d_in[12];
    const float* f2b  = (const float*)d_in[13];
    const float* a1ap = (const float*)d_in[14];
    const float* a2ap = (const float*)d_in[15];
    const float* a1pa = (const float*)d_in[16];
    const float* a2pa = (const float*)d_in[17];
    const float* a1pp = (const float*)d_in[18];
    const float* a2pp = (const float*)d_in[19];
    float* out = (float*)d_out;

    float *xa, *xp, *ha, *hp0, *hp1, *aggp1;
    int *rp_ap, *rp_pa, *rp_pp, *col_ap, *col_pa, *col_pp, *cnt, *bsum;
    int *cur_ap, *cur_pa, *cur_pp;
    float *h1a, *h1ap, *h1pp0, *h1pp1;
    cudaGetSymbolAddress((void**)&xa, g_xa);
    cudaGetSymbolAddress((void**)&xp, g_xp);
    cudaGetSymbolAddress((void**)&ha, g_ha);
    cudaGetSymbolAddress((void**)&hp0, g_hp0);
    cudaGetSymbolAddress((void**)&hp1, g_hp1);
    cudaGetSymbolAddress((void**)&aggp1, g_aggp1);
    cudaGetSymbolAddress((void**)&rp_ap, g_rp_ap);
    cudaGetSymbolAddress((void**)&rp_pa, g_rp_pa);
    cudaGetSymbolAddress((void**)&rp_pp, g_rp_pp);
    cudaGetSymbolAddress((void**)&col_ap, g_col_ap);
    cudaGetSymbolAddress((void**)&col_pa, g_col_pa);
    cudaGetSymbolAddress((void**)&col_pp, g_col_pp);
    cudaGetSymbolAddress((void**)&cnt, g_cnt);
    cudaGetSymbolAddress((void**)&bsum, g_bsum);
    cudaGetSymbolAddress((void**)&cur_ap, g_cur_ap);
    cudaGetSymbolAddress((void**)&cur_pa, g_cur_pa);
    cudaGetSymbolAddress((void**)&cur_pp, g_cur_pp);
    cudaGetSymbolAddress((void**)&h1a, g_h1a);
    cudaGetSymbolAddress((void**)&h1ap, g_h1ap);
    cudaGetSymbolAddress((void**)&h1pp0, g_h1pp0);
    cudaGetSymbolAddress((void**)&h1pp1, g_h1pp1);

    cudaStream_t st = 0;
    const int TB = 256;
    const int EB = cdiv(NE, TB);

    int* cntA = cnt;
    int* cntPa = cnt + N_A;
    int* cntPp = cnt + N_A + N_P;

    // 0: zero all histograms in one memset
    cudaMemsetAsync(cnt, 0, (N_A + 2 * N_P) * sizeof(int), st);
    // 1-3: histograms
    hist_k<<<EB, TB, 0, st>>>(ap_s, cntA, NE);
    hist_k<<<EB, TB, 0, st>>>(pa_s, cntPa, NE);
    hist_k<<<EB, TB, 0, st>>>(pp_s, cntPp, NE);
    // 4-5: input projections (+ initial h1 dots). Launch #5 = fc1_p (ncu capture).
    fc1_k<1><<<cdiv(N_A, 16), TB, 0, st>>>(x_a, f1aw, f1ab, xa, N_A, 512,
                                           a2pa + 0 * HID, (const float*)0, h1a, (float*)0);
    fc1_k<2><<<cdiv(N_P, 16), TB, 0, st>>>(x_p, f1pw, f1pb, xp, N_P, 256,
                                           a2ap + 0 * HID, a2pp + 0 * HID, h1ap, h1pp0);
    // CSR scans + scatters
    int nbA = cdiv(N_A, SCAN_B), nbP = cdiv(N_P, SCAN_B);
    int* bsA = bsum;
    int* bsPa = bsum + MAXBLK;
    int* bsPp = bsum + 2 * MAXBLK;

    scan1_k<<<nbA, SCAN_B, 0, st>>>(cntA, rp_ap, bsA, N_A);
    scan2_k<<<1, 128, 0, st>>>(bsA, nbA, rp_ap + N_A);
    scan3_k<<<cdiv(N_A, TB), TB, 0, st>>>(rp_ap, bsA, cur_ap, N_A);
    scatter_k<<<EB, TB, 0, st>>>(ap_s, ap_t, cur_ap, col_ap, NE);

    scan1_k<<<nbP, SCAN_B, 0, st>>>(cntPa, rp_pa, bsPa, N_P);
    scan2_k<<<1, 128, 0, st>>>(bsPa, nbP, rp_pa + N_P);
    scan3_k<<<cdiv(N_P, TB), TB, 0, st>>>(rp_pa, bsPa, cur_pa, N_P);
    scatter_k<<<EB, TB, 0, st>>>(pa_s, pa_t, cur_pa, col_pa, NE);

    scan1_k<<<nbP, SCAN_B, 0, st>>>(cntPp, rp_pp, bsPp, N_P);
    scan2_k<<<1, 128, 0, st>>>(bsPp, nbP, rp_pp + N_P);
    scan3_k<<<cdiv(N_P, TB), TB, 0, st>>>(rp_pp, bsPp, cur_pp, N_P);
    scatter_k<<<EB, TB, 0, st>>>(pp_s, pp_t, cur_pp, col_pp, NE);

    // hops
    const float* ha_cur = xa;   // hidden A (projected features at hop 0)
    const float* hp_cur = xp;
    float* hp_next = hp0;
    const float* h1pp_cur = h1pp0;
    float* h1pp_next = h1pp1;

    const int GA = cdiv(N_A, 8);   // 8 warps / 256-thread block
    const int GP = cdiv(N_P, 8);

    for (int i = 0; i < HOP; i++) {
        int donext = (i + 1 < HOP) ? 1 : 0;
        int ni = donext ? (i + 1) : i;   // dummy valid ptr at last hop
        // 1) p <- a aggregation (reads ha_cur) -> raw buffer
        agg_k<0><<<GP, TB, 0, st>>>(rp_pa, col_pa, h1a, (const float4*)ha_cur,
                                    (const float4*)xp, a1pa + i * HID, a2pa + i * HID,
                                    (float4*)aggp1, (const float4*)0,
                                    (const float*)0, (const float*)0,
                                    (float*)0, (float*)0, 0, N_P);
        // 2) a <- p aggregation -> ha = elu(agg), next h1a
        agg_k<1><<<GA, TB, 0, st>>>(rp_ap, col_ap, h1ap, (const float4*)hp_cur,
                                    (const float4*)xa, a1ap + i * HID, a2ap + i * HID,
                                    (float4*)ha, (const float4*)0,
                                    a2pa + ni * HID, (const float*)0,
                                    h1a, (float*)0, donext, N_A);
        // 3) p <- p aggregation -> hp_next = elu(0.5*(aggp1 + agg)), next h1ap/h1pp
        agg_k<2><<<GP, TB, 0, st>>>(rp_pp, col_pp, h1pp_cur, (const float4*)hp_cur,
                                    (const float4*)xp, a1pp + i * HID, a2pp + i * HID,
                                    (float4*)hp_next, (const float4*)aggp1,
                                    a2ap + ni * HID, a2pp + ni * HID,
                                    h1ap, h1pp_next, donext, N_P);
        // swap buffers
        ha_cur = ha;
        const float* t1 = hp_cur;
        hp_cur = hp_next;
        hp_next = (t1 == xp) ? hp1 : (float*)t1;
        const float* t2 = h1pp_cur;
        h1pp_cur = h1pp_next;
        h1pp_next = (float*)t2;
    }

    fc2_k<<<cdiv(N_A, 16), TB, 0, st>>>(ha, f2w, f2b, out, N_A);
}

// round 3
// speedup vs baseline: 1.5653x; 1.1265x over previous
#include <cuda_runtime.h>
#include <math.h>

#define N_A 50000
#define N_P 100000
#define HID 64
#define OUT_DIM 16
#define NE 2000000
#define HOP 3
#define SCAN_B 1024
#define MAXBLK 128

// ---------------- scratch (device globals) ----------------
__device__ float g_xa[(size_t)N_A * HID];
__device__ float g_xp[(size_t)N_P * HID];
__device__ float g_ha[(size_t)N_A * HID];
__device__ float g_hp0[(size_t)N_P * HID];
__device__ float g_hp1[(size_t)N_P * HID];
__device__ float g_aggp1[(size_t)N_P * HID];

__device__ int g_rp_ap[N_A + 1];
__device__ int g_rp_pa[N_P + 1];
__device__ int g_rp_pp[N_P + 1];
__device__ int g_col_ap[NE];
__device__ int g_col_pa[NE];
__device__ int g_col_pp[NE];
__device__ int g_cnt[N_A + 2 * N_P];
__device__ int g_cur_ap[N_A];
__device__ int g_cur_pa[N_P];
__device__ int g_cur_pp[N_P];
__device__ int g_bsum[3 * MAXBLK];

__device__ float g_h1a[N_A];
__device__ float g_h1ap[N_P];
__device__ float g_h1pp0[N_P];
__device__ float g_h1pp1[N_P];

// ---------------- CSR build ----------------
__global__ void hist_k(const int* __restrict__ s, int* cnt, int e) {
    int i = blockIdx.x * blockDim.x + threadIdx.x;
    if (i < e) atomicAdd(&cnt[s[i]], 1);
}

__global__ void scan1_k(const int* __restrict__ cnt, int* __restrict__ rp,
                        int* __restrict__ bsum, int n) {
    __shared__ int sd[SCAN_B];
    int tid = threadIdx.x;
    int i = blockIdx.x * SCAN_B + tid;
    int v = (i < n) ? cnt[i] : 0;
    sd[tid] = v;
    __syncthreads();
#pragma unroll
    for (int o = 1; o < SCAN_B; o <<= 1) {
        int t = (tid >= o) ? sd[tid - o] : 0;
        __syncthreads();
        sd[tid] += t;
        __syncthreads();
    }
    if (i < n) rp[i] = sd[tid] - v;
    if (tid == SCAN_B - 1) bsum[blockIdx.x] = sd[tid];
}

__global__ void scan2_k(int* bsum, int nb, int* rp_last) {
    __shared__ int sd[128];
    int tid = threadIdx.x;
    int v = (tid < nb) ? bsum[tid] : 0;
    sd[tid] = v;
    __syncthreads();
#pragma unroll
    for (int o = 1; o < 128; o <<= 1) {
        int t = (tid >= o) ? sd[tid - o] : 0;
        __syncthreads();
        sd[tid] += t;
        __syncthreads();
    }
    if (tid < nb) bsum[tid] = sd[tid] - v;
    if (tid == 127) *rp_last = sd[127];
}

__global__ void scan3_k(int* __restrict__ rp, const int* __restrict__ bsum,
                        int* __restrict__ cur, int n) {
    int i = blockIdx.x * blockDim.x + threadIdx.x;
    if (i < n) {
        int r = rp[i] + bsum[i >> 10];
        rp[i] = r;
        cur[i] = r;
    }
}

__global__ void scatter_k(const int* __restrict__ s, const int* __restrict__ t,
                          int* cursor, int* __restrict__ col, int e) {
    int i = blockIdx.x * blockDim.x + threadIdx.x;
    if (i < e) {
        int p = atomicAdd(&cursor[s[i]], 1);
        col[p] = t[i];
    }
}

// ---------------- fc1 v3: smem-tiled register-blocked GEMM + relu + h1 dots ----------
// Block 256 threads = 128-node x 64-col tile. Thread: 4 nodes x 8 cols.
// cg = tx&7 (col group, 8 cols), ng = tx>>3 (node group, 4 nodes).
#define XS_PITCH 36
template <int NDOT>
__global__ void __launch_bounds__(256)
fc1_k(const float* __restrict__ x, const float* __restrict__ W,
      const float* __restrict__ b, float* __restrict__ out,
      int n, int D,
      const float* __restrict__ av1, const float* __restrict__ av2,
      float* __restrict__ h1o1, float* __restrict__ h1o2) {
    __shared__ float Ws[32 * 64];
    __shared__ float Xs[128 * XS_PITCH];
    int tx = threadIdx.x;
    int cg = tx & 7;
    int ng = tx >> 3;
    int c8 = cg * 8;
    int base = blockIdx.x * 128;

    float acc[4][8];
#pragma unroll
    for (int i = 0; i < 4; i++)
#pragma unroll
        for (int c = 0; c < 8; c++) acc[i][c] = 0.f;

    for (int k0 = 0; k0 < D; k0 += 32) {
        // load W tile [32][64]
#pragma unroll
        for (int i = 0; i < 2; i++) {
            int idx = tx + i * 256;          // 512 float4
            int row = idx >> 4;
            int c4 = (idx & 15) << 2;
            *(float4*)&Ws[row * 64 + c4] =
                __ldg((const float4*)(W + (size_t)(k0 + row) * HID + c4));
        }
        // load X tile [128][32] (row-major, pitch 36)
#pragma unroll
        for (int i = 0; i < 4; i++) {
            int idx = tx + i * 256;          // 1024 float4
            int node = idx >> 3;
            int kq = idx & 7;
            int gn = base + node;
            float4 v = make_float4(0.f, 0.f, 0.f, 0.f);
            if (gn < n) v = __ldg((const float4*)(x + (size_t)gn * D + k0 + kq * 4));
            *(float4*)&Xs[node * XS_PITCH + kq * 4] = v;
        }
        __syncthreads();

#pragma unroll
        for (int k = 0; k < 32; k += 4) {
            float4 w0a = *(float4*)&Ws[(k + 0) * 64 + c8];
            float4 w0b = *(float4*)&Ws[(k + 0) * 64 + c8 + 4];
            float4 w1a = *(float4*)&Ws[(k + 1) * 64 + c8];
            float4 w1b = *(float4*)&Ws[(k + 1) * 64 + c8 + 4];
            float4 w2a = *(float4*)&Ws[(k + 2) * 64 + c8];
            float4 w2b = *(float4*)&Ws[(k + 2) * 64 + c8 + 4];
            float4 w3a = *(float4*)&Ws[(k + 3) * 64 + c8];
            float4 w3b = *(float4*)&Ws[(k + 3) * 64 + c8 + 4];
#pragma unroll
            for (int i = 0; i < 4; i++) {
                float4 xv = *(float4*)&Xs[(ng * 4 + i) * XS_PITCH + k];
                acc[i][0] = fmaf(xv.x, w0a.x, acc[i][0]);
                acc[i][1] = fmaf(xv.x, w0a.y, acc[i][1]);
                acc[i][2] = fmaf(xv.x, w0a.z, acc[i][2]);
                acc[i][3] = fmaf(xv.x, w0a.w, acc[i][3]);
                acc[i][4] = fmaf(xv.x, w0b.x, acc[i][4]);
                acc[i][5] = fmaf(xv.x, w0b.y, acc[i][5]);
                acc[i][6] = fmaf(xv.x, w0b.z, acc[i][6]);
                acc[i][7] = fmaf(xv.x, w0b.w, acc[i][7]);

                acc[i][0] = fmaf(xv.y, w1a.x, acc[i][0]);
                acc[i][1] = fmaf(xv.y, w1a.y, acc[i][1]);
                acc[i][2] = fmaf(xv.y, w1a.z, acc[i][2]);
                acc[i][3] = fmaf(xv.y, w1a.w, acc[i][3]);
                acc[i][4] = fmaf(xv.y, w1b.x, acc[i][4]);
                acc[i][5] = fmaf(xv.y, w1b.y, acc[i][5]);
                acc[i][6] = fmaf(xv.y, w1b.z, acc[i][6]);
                acc[i][7] = fmaf(xv.y, w1b.w, acc[i][7]);

                acc[i][0] = fmaf(xv.z, w2a.x, acc[i][0]);
                acc[i][1] = fmaf(xv.z, w2a.y, acc[i][1]);
                acc[i][2] = fmaf(xv.z, w2a.z, acc[i][2]);
                acc[i][3] = fmaf(xv.z, w2a.w, acc[i][3]);
                acc[i][4] = fmaf(xv.z, w2b.x, acc[i][4]);
                acc[i][5] = fmaf(xv.z, w2b.y, acc[i][5]);
                acc[i][6] = fmaf(xv.z, w2b.z, acc[i][6]);
                acc[i][7] = fmaf(xv.z, w2b.w, acc[i][7]);

                acc[i][0] = fmaf(xv.w, w3a.x, acc[i][0]);
                acc[i][1] = fmaf(xv.w, w3a.y, acc[i][1]);
                acc[i][2] = fmaf(xv.w, w3a.z, acc[i][2]);
                acc[i][3] = fmaf(xv.w, w3a.w, acc[i][3]);
                acc[i][4] = fmaf(xv.w, w3b.x, acc[i][4]);
                acc[i][5] = fmaf(xv.w, w3b.y, acc[i][5]);
                acc[i][6] = fmaf(xv.w, w3b.z, acc[i][6]);
                acc[i][7] = fmaf(xv.w, w3b.w, acc[i][7]);
            }
        }
        __syncthreads();
    }

    // epilogue: bias + relu + store + fused h1 dots
    float4 bv0 = __ldg((const float4*)(b + c8));
    float4 bv1 = __ldg((const float4*)(b + c8 + 4));
    float4 a10 = __ldg((const float4*)(av1 + c8));
    float4 a11 = __ldg((const float4*)(av1 + c8 + 4));
    float4 a20 = make_float4(0.f, 0.f, 0.f, 0.f), a21 = a20;
    if (NDOT == 2) {
        a20 = __ldg((const float4*)(av2 + c8));
        a21 = __ldg((const float4*)(av2 + c8 + 4));
    }
#pragma unroll
    for (int i = 0; i < 4; i++) {
        int gn = base + ng * 4 + i;
        float4 r0, r1;
        r0.x = fmaxf(acc[i][0] + bv0.x, 0.f);
        r0.y = fmaxf(acc[i][1] + bv0.y, 0.f);
        r0.z = fmaxf(acc[i][2] + bv0.z, 0.f);
        r0.w = fmaxf(acc[i][3] + bv0.w, 0.f);
        r1.x = fmaxf(acc[i][4] + bv1.x, 0.f);
        r1.y = fmaxf(acc[i][5] + bv1.y, 0.f);
        r1.z = fmaxf(acc[i][6] + bv1.z, 0.f);
        r1.w = fmaxf(acc[i][7] + bv1.w, 0.f);
        if (gn < n) {
            *(float4*)(out + (size_t)gn * HID + c8) = r0;
            *(float4*)(out + (size_t)gn * HID + c8 + 4) = r1;
        }
        float d1 = r0.x * a10.x + r0.y * a10.y + r0.z * a10.z + r0.w * a10.w
                 + r1.x * a11.x + r1.y * a11.y + r1.z * a11.z + r1.w * a11.w;
        float d2 = 0.f;
        if (NDOT == 2)
            d2 = r0.x * a20.x + r0.y * a20.y + r0.z * a20.z + r0.w * a20.w
               + r1.x * a21.x + r1.y * a21.y + r1.z * a21.z + r1.w * a21.w;
#pragma unroll
        for (int o = 4; o; o >>= 1) {
            d1 += __shfl_xor_sync(0xffffffffu, d1, o);
            if (NDOT == 2) d2 += __shfl_xor_sync(0xffffffffu, d2, o);
        }
        if (cg == 0 && gn < n) {
            h1o1[gn] = d1;
            if (NDOT == 2) h1o2[gn] = d2;
        }
    }
}

// ---------------- fused edge aggregation (unchanged from R2) ----------------
template <int MODE>
__global__ void __launch_bounds__(256)
agg_k(const int* __restrict__ rowptr, const int* __restrict__ col,
      const float* __restrict__ h1, const float4* __restrict__ h4,
      const float4* __restrict__ x4p,
      const float* __restrict__ a1, const float* __restrict__ a2,
      float4* __restrict__ out, const float4* __restrict__ other,
      const float* __restrict__ a2n1, const float* __restrict__ a2n2,
      float* __restrict__ h1n1, float* __restrict__ h1n2,
      int donext, int ns) {
    int n = (blockIdx.x * blockDim.x + threadIdx.x) >> 5;
    if (n >= ns) return;
    int lane = threadIdx.x & 31;
    int c = lane & 15;
    int hs = lane & 16;

    float4 xv = __ldg(x4p + (size_t)n * 16 + c);
    float4 a1v = __ldg((const float4*)a1 + c);
    float4 a2v = __ldg((const float4*)a2 + c);
    float p1 = xv.x * a1v.x + xv.y * a1v.y + xv.z * a1v.z + xv.w * a1v.w;
    float p2 = xv.x * a2v.x + xv.y * a2v.y + xv.z * a2v.z + xv.w * a2v.w;
#pragma unroll
    for (int o = 8; o; o >>= 1) {
        p1 += __shfl_xor_sync(0xffffffffu, p1, o);
        p2 += __shfl_xor_sync(0xffffffffu, p2, o);
    }
    float x1n = p1;
    float sc = p1 + p2;
    sc = sc >= 0.f ? sc : 0.2f * sc;
    float w2n = __expf(sc);

    int beg = __ldg(rowptr + n), end = __ldg(rowptr + n + 1);
    float4 acc = make_float4(0.f, 0.f, 0.f, 0.f);
    float sumw = 0.f;

    int j = beg;
    for (; j + 32 <= end; j += 32) {
        int tl = __ldg(col + j + lane);
        float s = x1n + __ldg(h1 + tl);
        s = s >= 0.f ? s : 0.2f * s;
        float wl = __expf(s);
#pragma unroll
        for (int k = 0; k < 16; k++) {
            float w = __shfl_sync(0xffffffffu, wl, hs + k);
            int t = __shfl_sync(0xffffffffu, tl, hs + k);
            float4 hv = __ldg(h4 + (size_t)t * 16 + c);
            acc.x = fmaf(w, hv.x, acc.x);
            acc.y = fmaf(w, hv.y, acc.y);
            acc.z = fmaf(w, hv.z, acc.z);
            acc.w = fmaf(w, hv.w, acc.w);
            sumw += w;
        }
    }
    if (j < end) {
        int idx = j + lane;
        int tl = 0;
        float wl = 0.f;
        if (idx < end) {
            tl = __ldg(col + idx);
            float s = x1n + __ldg(h1 + tl);
            s = s >= 0.f ? s : 0.2f * s;
            wl = __expf(s);
        }
#pragma unroll
        for (int k = 0; k < 16; k++) {
            float w = __shfl_sync(0xffffffffu, wl, hs + k);
            int t = __shfl_sync(0xffffffffu, tl, hs + k);
            if (j + hs + k < end) {
                float4 hv = __ldg(h4 + (size_t)t * 16 + c);
                acc.x = fmaf(w, hv.x, acc.x);
                acc.y = fmaf(w, hv.y, acc.y);
                acc.z = fmaf(w, hv.z, acc.z);
                acc.w = fmaf(w, hv.w, acc.w);
                sumw += w;
            }
        }
    }

    acc.x += __shfl_xor_sync(0xffffffffu, acc.x, 16);
    acc.y += __shfl_xor_sync(0xffffffffu, acc.y, 16);
    acc.z += __shfl_xor_sync(0xffffffffu, acc.z, 16);
    acc.w += __shfl_xor_sync(0xffffffffu, acc.w, 16);
    sumw += __shfl_xor_sync(0xffffffffu, sumw, 16);

    sumw += w2n;
    acc.x = fmaf(w2n, xv.x, acc.x);
    acc.y = fmaf(w2n, xv.y, acc.y);
    acc.z = fmaf(w2n, xv.z, acc.z);
    acc.w = fmaf(w2n, xv.w, acc.w);

    float inv = 1.f / sumw;
    float4 r = make_float4(acc.x * inv, acc.y * inv, acc.z * inv, acc.w * inv);

    if (MODE == 0) {
        if (!hs) out[(size_t)n * 16 + c] = r;
        return;
    }
    if (MODE == 2) {
        float4 o = __ldg(other + (size_t)n * 16 + c);
        r.x = 0.5f * (r.x + o.x);
        r.y = 0.5f * (r.y + o.y);
        r.z = 0.5f * (r.z + o.z);
        r.w = 0.5f * (r.w + o.w);
    }
    float4 v;
    v.x = r.x > 0.f ? r.x : expm1f(r.x);
    v.y = r.y > 0.f ? r.y : expm1f(r.y);
    v.z = r.z > 0.f ? r.z : expm1f(r.z);
    v.w = r.w > 0.f ? r.w : expm1f(r.w);
    if (!hs) out[(size_t)n * 16 + c] = v;

    if (donext) {
        float4 b1 = __ldg((const float4*)a2n1 + c);
        float d1 = v.x * b1.x + v.y * b1.y + v.z * b1.z + v.w * b1.w;
        float d2 = 0.f;
        if (MODE == 2) {
            float4 b2 = __ldg((const float4*)a2n2 + c);
            d2 = v.x * b2.x + v.y * b2.y + v.z * b2.z + v.w * b2.w;
        }
#pragma unroll
        for (int o = 8; o; o >>= 1) {
            d1 += __shfl_xor_sync(0xffffffffu, d1, o);
            if (MODE == 2) d2 += __shfl_xor_sync(0xffffffffu, d2, o);
        }
        if (lane == 0) {
            h1n1[n] = d1;
            if (MODE == 2) h1n2[n] = d2;
        }
    }
}

// ---------------- fc2 ----------------
__global__ void fc2_k(const float* __restrict__ h, const float* __restrict__ W,
                      const float* __restrict__ b, float* __restrict__ out, int n) {
    int node = blockIdx.x * 16 + (threadIdx.x >> 4);
    int c = threadIdx.x & 15;
    if (node >= n) return;
    float acc = b[c];
    const float* hr = h + (size_t)node * HID;
#pragma unroll
    for (int k = 0; k < HID; k++)
        acc = fmaf(__ldg(hr + k), __ldg(W + k * OUT_DIM + c), acc);
    out[(size_t)node * OUT_DIM + c] = acc;
}

// ---------------- host ----------------
static inline int cdiv(int a, int b) { return (a + b - 1) / b; }

extern "C" void kernel_launch(void* const* d_in, const int* in_sizes, int n_in,
                              void* d_out, int out_size) {
    const float* x_a  = (const float*)d_in[0];
    const float* x_p  = (const float*)d_in[1];
    const int*   ap_s = (const int*)d_in[2];
    const int*   ap_t = (const int*)d_in[3];
    const int*   pa_s = (const int*)d_in[4];
    const int*   pa_t = (const int*)d_in[5];
    const int*   pp_s = (const int*)d_in[6];
    const int*   pp_t = (const int*)d_in[7];
    const float* f1aw = (const float*)d_in[8];
    const float* f1ab = (const float*)d_in[9];
    const float* f1pw = (const float*)d_in[10];
    const float* f1pb = (const float*)d_in[11];
    const float* f2w  = (const float*)d_in[12];
    const float* f2b  = (const float*)d_in[13];
    const float* a1ap = (const float*)d_in[14];
    const float* a2ap = (const float*)d_in[15];
    const float* a1pa = (const float*)d_in[16];
    const float* a2pa = (const float*)d_in[17];
    const float* a1pp = (const float*)d_in[18];
    const float* a2pp = (const float*)d_in[19];
    float* out = (float*)d_out;

    float *xa, *xp, *ha, *hp0, *hp1, *aggp1;
    int *rp_ap, *rp_pa, *rp_pp, *col_ap, *col_pa, *col_pp, *cnt, *bsum;
    int *cur_ap, *cur_pa, *cur_pp;
    float *h1a, *h1ap, *h1pp0, *h1pp1;
    cudaGetSymbolAddress((void**)&xa, g_xa);
    cudaGetSymbolAddress((void**)&xp, g_xp);
    cudaGetSymbolAddress((void**)&ha, g_ha);
    cudaGetSymbolAddress((void**)&hp0, g_hp0);
    cudaGetSymbolAddress((void**)&hp1, g_hp1);
    cudaGetSymbolAddress((void**)&aggp1, g_aggp1);
    cudaGetSymbolAddress((void**)&rp_ap, g_rp_ap);
    cudaGetSymbolAddress((void**)&rp_pa, g_rp_pa);
    cudaGetSymbolAddress((void**)&rp_pp, g_rp_pp);
    cudaGetSymbolAddress((void**)&col_ap, g_col_ap);
    cudaGetSymbolAddress((void**)&col_pa, g_col_pa);
    cudaGetSymbolAddress((void**)&col_pp, g_col_pp);
    cudaGetSymbolAddress((void**)&cnt, g_cnt);
    cudaGetSymbolAddress((void**)&bsum, g_bsum);
    cudaGetSymbolAddress((void**)&cur_ap, g_cur_ap);
    cudaGetSymbolAddress((void**)&cur_pa, g_cur_pa);
    cudaGetSymbolAddress((void**)&cur_pp, g_cur_pp);
    cudaGetSymbolAddress((void**)&h1a, g_h1a);
    cudaGetSymbolAddress((void**)&h1ap, g_h1ap);
    cudaGetSymbolAddress((void**)&h1pp0, g_h1pp0);
    cudaGetSymbolAddress((void**)&h1pp1, g_h1pp1);

    cudaStream_t st = 0;
    const int TB = 256;
    const int EB = cdiv(NE, TB);

    int* cntA = cnt;
    int* cntPa = cnt + N_A;
    int* cntPp = cnt + N_A + N_P;

    cudaMemsetAsync(cnt, 0, (N_A + 2 * N_P) * sizeof(int), st);
    hist_k<<<EB, TB, 0, st>>>(ap_s, cntA, NE);
    hist_k<<<EB, TB, 0, st>>>(pa_s, cntPa, NE);
    hist_k<<<EB, TB, 0, st>>>(pp_s, cntPp, NE);
    fc1_k<1><<<cdiv(N_A, 128), TB, 0, st>>>(x_a, f1aw, f1ab, xa, N_A, 512,
                                            a2pa + 0 * HID, (const float*)0, h1a, (float*)0);
    fc1_k<2><<<cdiv(N_P, 128), TB, 0, st>>>(x_p, f1pw, f1pb, xp, N_P, 256,
                                            a2ap + 0 * HID, a2pp + 0 * HID, h1ap, h1pp0);

    int nbA = cdiv(N_A, SCAN_B), nbP = cdiv(N_P, SCAN_B);
    int* bsA = bsum;
    int* bsPa = bsum + MAXBLK;
    int* bsPp = bsum + 2 * MAXBLK;

    scan1_k<<<nbA, SCAN_B, 0, st>>>(cntA, rp_ap, bsA, N_A);
    scan2_k<<<1, 128, 0, st>>>(bsA, nbA, rp_ap + N_A);
    scan3_k<<<cdiv(N_A, TB), TB, 0, st>>>(rp_ap, bsA, cur_ap, N_A);
    scatter_k<<<EB, TB, 0, st>>>(ap_s, ap_t, cur_ap, col_ap, NE);

    scan1_k<<<nbP, SCAN_B, 0, st>>>(cntPa, rp_pa, bsPa, N_P);
    scan2_k<<<1, 128, 0, st>>>(bsPa, nbP, rp_pa + N_P);
    scan3_k<<<cdiv(N_P, TB), TB, 0, st>>>(rp_pa, bsPa, cur_pa, N_P);
    scatter_k<<<EB, TB, 0, st>>>(pa_s, pa_t, cur_pa, col_pa, NE);

    scan1_k<<<nbP, SCAN_B, 0, st>>>(cntPp, rp_pp, bsPp, N_P);
    scan2_k<<<1, 128, 0, st>>>(bsPp, nbP, rp_pp + N_P);
    scan3_k<<<cdiv(N_P, TB), TB, 0, st>>>(rp_pp, bsPp, cur_pp, N_P);
    scatter_k<<<EB, TB, 0, st>>>(pp_s, pp_t, cur_pp, col_pp, NE);

    const float* ha_cur = xa;
    const float* hp_cur = xp;
    float* hp_next = hp0;
    const float* h1pp_cur = h1pp0;
    float* h1pp_next = h1pp1;

    const int GA = cdiv(N_A, 8);
    const int GP = cdiv(N_P, 8);

    for (int i = 0; i < HOP; i++) {
        int donext = (i + 1 < HOP) ? 1 : 0;
        int ni = donext ? (i + 1) : i;
        agg_k<0><<<GP, TB, 0, st>>>(rp_pa, col_pa, h1a, (const float4*)ha_cur,
                                    (const float4*)xp, a1pa + i * HID, a2pa + i * HID,
                                    (float4*)aggp1, (const float4*)0,
                                    (const float*)0, (const float*)0,
                                    (float*)0, (float*)0, 0, N_P);
        agg_k<1><<<GA, TB, 0, st>>>(rp_ap, col_ap, h1ap, (const float4*)hp_cur,
                                    (const float4*)xa, a1ap + i * HID, a2ap + i * HID,
                                    (float4*)ha, (const float4*)0,
                                    a2pa + ni * HID, (const float*)0,
                                    h1a, (float*)0, donext, N_A);
        agg_k<2><<<GP, TB, 0, st>>>(rp_pp, col_pp, h1pp_cur, (const float4*)hp_cur,
                                    (const float4*)xp, a1pp + i * HID, a2pp + i * HID,
                                    (float4*)hp_next, (const float4*)aggp1,
                                    a2ap + ni * HID, a2pp + ni * HID,
                                    h1ap, h1pp_next, donext, N_P);
        ha_cur = ha;
        const float* t1 = hp_cur;
        hp_cur = hp_next;
        hp_next = (t1 == xp) ? hp1 : (float*)t1;
        const float* t2 = h1pp_cur;
        h1pp_cur = h1pp_next;
        h1pp_next = (float*)t2;
    }

    fc2_k<<<cdiv(N_A, 16), TB, 0, st>>>(ha, f2w, f2b, out, N_A);
}